// round 8
// baseline (speedup 1.0000x reference)
#include <cuda_runtime.h>
#include <math.h>
#include <stdint.h>

#define B_SZ   32768
#define NW     30
#define VOCAB  32000
#define WD     300
#define CH     400
#define AD     200

#define KQ_PAD 304      // 300 padded to 16-mult
#define KF_PAD 912      // 3 x 304
#define NB_PAD 640      // Mt rows padded to 128-mult

// ---------------- scratch (static device globals; no allocation) ----------------
__device__ __align__(16) float g_embP[VOCAB * KQ_PAD];     // permuted/padded tf32 A (Q gemm)
__device__ __align__(16) float g_MtP[NB_PAD * KQ_PAD];     // permuted/padded tf32 Bt (Q gemm)
__device__ __align__(16) float g_cvb[AD];
__device__ __align__(16) float g_Q[VOCAB * 600];           // [tok][k*200+a]
__device__ __align__(16) float g_aT[NW * B_SZ];
__device__ float g_mx[NW];
__device__ float g_isum[NW];
__device__ __align__(16) float g_GP[(size_t)B_SZ * KF_PAD];  // permuted/padded tf32 A (final)
__device__ float g_salpha[B_SZ];
__device__ __align__(16) float g_Wc2tP[CH * KF_PAD];       // permuted/padded tf32 Bt (final)

__device__ __forceinline__ uint32_t f2tf32(float x)
{
    uint32_t r;
    asm("cvt.rna.tf32.f32 %0, %1;" : "=r"(r) : "f"(x));
    return r;
}
__device__ __forceinline__ float rtf32(float x) { return __uint_as_float(f2tf32(x)); }

__device__ __forceinline__ float ftanh(float x)
{
    float e = __expf(2.f * x);
    return 1.f - __fdividef(2.f, e + 1.f);
}

// stored position p within a 16-block holds logical k = permL(p)
__device__ __forceinline__ int permL(int p)
{
    return (p & 8) | ((p >> 1) & 3) | ((p & 1) << 2);
}

// ---------------- prep kernels ----------------
// A for Q-gemm: tf32-rounded emb, K padded to 304, k-pair permuted
__global__ void prep_embP_kernel(const float* __restrict__ emb)
{
    int idx = blockIdx.x * blockDim.x + threadIdx.x;
    if (idx >= VOCAB * KQ_PAD) return;
    int row = idx / KQ_PAD;
    int p   = idx % KQ_PAD;
    int k   = (p & ~15) | permL(p & 15);
    g_embP[idx] = (k < WD) ? rtf32(emb[row * WD + k]) : 0.f;
}

// Bt for Q-gemm: Mt[n][i] = sum_o conv_w[o,i,ks]*v[o,a], n = ks*200+a; padded+permuted
__global__ void prep_MtP_kernel(const float* __restrict__ conv_w, const float* __restrict__ v)
{
    int idx = blockIdx.x * blockDim.x + threadIdx.x;
    if (idx >= NB_PAD * KQ_PAD) return;
    int n = idx / KQ_PAD;
    int p = idx % KQ_PAD;
    float val = 0.f;
    if (n < 600) {
        int i = (p & ~15) | permL(p & 15);
        if (i < WD) {
            int ks = n / 200;
            int a  = n % 200;
            float s = 0.f;
            #pragma unroll 4
            for (int o = 0; o < CH; o++)
                s += conv_w[o * (WD * 3) + i * 3 + ks] * v[o * AD + a];
            val = rtf32(s);
        }
    }
    g_MtP[idx] = val;
}

__global__ void prep_cvb_kernel(const float* __restrict__ conv_b,
                                const float* __restrict__ v,
                                const float* __restrict__ vb)
{
    int a = blockIdx.x * blockDim.x + threadIdx.x;
    if (a >= AD) return;
    float s = vb[a];
    for (int o = 0; o < CH; o++) s += conv_b[o] * v[o * AD + a];
    g_cvb[a] = s;
}

// Bt for final gemm: Wc2t[o][slice*304 + perm(i)] = conv_w[o,i,slice]
__global__ void prep_Wc2tP_kernel(const float* __restrict__ conv_w)
{
    int idx = blockIdx.x * blockDim.x + threadIdx.x;
    if (idx >= CH * KF_PAD) return;
    int o  = idx / KF_PAD;
    int p  = idx % KF_PAD;
    int sl = p / KQ_PAD;
    int pp = p % KQ_PAD;
    int i  = (pp & ~15) | permL(pp & 15);
    g_Wc2tP[idx] = (i < WD) ? rtf32(conv_w[o * 900 + i * 3 + sl]) : 0.f;
}

// ================= tf32 mma.sync GEMM, k-paired layouts, guard-free cp.async ======
// C[M,N] = A[M,Kp] @ Bt[Nb,Kp]^T (+ rs[m]*bias[n]); A,Bt pre-rounded tf32 bits in
// k-pair permuted layout, Kp multiple of 16, Bt rows padded to BN-mult.
// Block 128 x BN, 128 threads (4 warps 2x2), warp tile 64 x BN/2.

__device__ __forceinline__ void mma_tf32(float* c,
                                         uint32_t a0, uint32_t a1, uint32_t a2, uint32_t a3,
                                         uint32_t b0, uint32_t b1)
{
    asm volatile(
        "mma.sync.aligned.m16n8k8.row.col.f32.tf32.tf32.f32 "
        "{%0,%1,%2,%3}, {%4,%5,%6,%7}, {%8,%9}, {%0,%1,%2,%3};\n"
        : "+f"(c[0]), "+f"(c[1]), "+f"(c[2]), "+f"(c[3])
        : "r"(a0), "r"(a1), "r"(a2), "r"(a3), "r"(b0), "r"(b1));
}

__device__ __forceinline__ void cp16(uint32_t dst, const void* src)
{
    asm volatile("cp.async.cg.shared.global [%0], [%1], 16;\n"
                 :: "r"(dst), "l"(src));
}

#define STAGES 4
#define ROW_W 20      // 16 k-words + 4 pad (80B rows, 16B-aligned for cp.async)

template<int BN>
__global__ __launch_bounds__(128, (BN == 80) ? 3 : 2)
void tgemm_kernel(const float* __restrict__ A, const float* __restrict__ Bt,
                  float* __restrict__ C, int M, int N, int Kp,
                  const float* __restrict__ rs, const float* __restrict__ bias)
{
    constexpr int NT    = BN / 16;               // n8 tiles per warp
    constexpr int BCHNK = BN * 4;                // 16B chunks per B panel
    constexpr int BRND  = (BCHNK + 127) / 128;

    extern __shared__ __align__(16) uint32_t smem[];
    uint32_t* Asm = smem;                            // [STAGES][128][ROW_W]
    uint32_t* Bsm = smem + STAGES * 128 * ROW_W;     // [STAGES][BN][ROW_W]
    const uint32_t as_base = (uint32_t)__cvta_generic_to_shared(Asm);
    const uint32_t bs_base = (uint32_t)__cvta_generic_to_shared(Bsm);

    const int tid    = threadIdx.x;
    const int lane   = tid & 31;
    const int warp   = tid >> 5;
    const int warp_m = warp & 1;
    const int warp_n = warp >> 1;
    const int m0 = blockIdx.y * 128;
    const int n0 = blockIdx.x * BN;

    const int nIter = Kp >> 4;

    float acc[4][NT][4];
    #pragma unroll
    for (int mt = 0; mt < 4; mt++)
        #pragma unroll
        for (int nt = 0; nt < NT; nt++)
            #pragma unroll
            for (int i = 0; i < 4; i++) acc[mt][nt][i] = 0.f;

    auto issue_panel = [&](int pnl) {
        const int s   = pnl & (STAGES - 1);
        const int kk0 = pnl * 16;
        // A: 128 rows x 4 chunks = 512 -> 4 per thread
        #pragma unroll
        for (int r = 0; r < 4; r++) {
            const int idx = tid + r * 128;
            const int row = idx >> 2;
            const int ch  = idx & 3;
            const float* src = A + (size_t)(m0 + row) * Kp + kk0 + ch * 4;
            cp16(as_base + (((s * 128 + row) * ROW_W) + ch * 4) * 4, src);
        }
        // B: BN rows x 4 chunks
        #pragma unroll
        for (int r = 0; r < BRND; r++) {
            const int idx = tid + r * 128;
            if (BCHNK % 128 == 0 || idx < BCHNK) {
                const int row = idx >> 2;
                const int ch  = idx & 3;
                const float* src = Bt + (size_t)(n0 + row) * Kp + kk0 + ch * 4;
                cp16(bs_base + (((s * BN + row) * ROW_W) + ch * 4) * 4, src);
            }
        }
        asm volatile("cp.async.commit_group;\n");
    };

    issue_panel(0);
    issue_panel(1);
    issue_panel(2);

    for (int it = 0; it < nIter; ++it) {
        asm volatile("cp.async.wait_group %0;\n" :: "n"(STAGES - 2));
        __syncthreads();

        const int s = it & (STAGES - 1);
        const uint32_t* Asb = Asm + s * 128 * ROW_W;
        const uint32_t* Bsb = Bsm + s * BN * ROW_W;

        #pragma unroll
        for (int ks = 0; ks < 2; ks++) {
            const int kof = ks * 8 + (lane & 3) * 2;   // word offset of (k, k+4) pair
            uint32_t af[4][4];
            uint32_t bf[NT][2];
            #pragma unroll
            for (int mt = 0; mt < 4; mt++) {
                const int rb = warp_m * 64 + mt * 16 + (lane >> 2);
                uint2 lo = *reinterpret_cast<const uint2*>(&Asb[rb * ROW_W + kof]);
                uint2 hi = *reinterpret_cast<const uint2*>(&Asb[(rb + 8) * ROW_W + kof]);
                af[mt][0] = lo.x;
                af[mt][1] = hi.x;
                af[mt][2] = lo.y;
                af[mt][3] = hi.y;
            }
            #pragma unroll
            for (int nt = 0; nt < NT; nt++) {
                const int nc = warp_n * (BN / 2) + nt * 8 + (lane >> 2);
                uint2 bv = *reinterpret_cast<const uint2*>(&Bsb[nc * ROW_W + kof]);
                bf[nt][0] = bv.x;
                bf[nt][1] = bv.y;
            }
            #pragma unroll
            for (int mt = 0; mt < 4; mt++)
                #pragma unroll
                for (int nt = 0; nt < NT; nt++)
                    mma_tf32(acc[mt][nt], af[mt][0], af[mt][1], af[mt][2], af[mt][3],
                             bf[nt][0], bf[nt][1]);
        }

        if (it + STAGES - 1 < nIter) {
            issue_panel(it + STAGES - 1);
        } else {
            asm volatile("cp.async.commit_group;\n");
        }
    }

    // ---- epilogue ----
    #pragma unroll
    for (int mt = 0; mt < 4; mt++) {
        const int row0 = m0 + warp_m * 64 + mt * 16 + (lane >> 2);
        const int row1 = row0 + 8;
        const float r0 = rs ? rs[row0] : 0.f;
        const float r1 = rs ? rs[row1] : 0.f;
        #pragma unroll
        for (int nt = 0; nt < NT; nt++) {
            const int col = n0 + warp_n * (BN / 2) + nt * 8 + (lane & 3) * 2;
            if (col < N) {
                float v0 = acc[mt][nt][0], v1 = acc[mt][nt][1];
                float v2 = acc[mt][nt][2], v3 = acc[mt][nt][3];
                if (bias) {
                    const float b0 = bias[col], b1 = bias[col + 1];
                    v0 += r0 * b0; v1 += r0 * b1;
                    v2 += r1 * b0; v3 += r1 * b1;
                }
                *reinterpret_cast<float2*>(C + (size_t)row0 * N + col) = make_float2(v0, v1);
                *reinterpret_cast<float2*>(C + (size_t)row1 * N + col) = make_float2(v2, v3);
            }
        }
    }
}

#define SMEM2(BN) (STAGES * (128 * ROW_W + (BN) * ROW_W) * 4)

// ---------------- scores ----------------
__global__ __launch_bounds__(256)
void score_kernel(const int* __restrict__ tok, const float* __restrict__ qv)
{
    __shared__ float4 sq[AD / 4];
    __shared__ float4 scvb[AD / 4];
    __shared__ int stok[8][NW];

    const int tid = threadIdx.x;
    const int wid = tid >> 5;
    const int lane = tid & 31;
    const int b = blockIdx.x * 8 + wid;

    if (tid < AD / 4) {
        sq[tid]   = reinterpret_cast<const float4*>(qv)[tid];
        scvb[tid] = reinterpret_cast<const float4*>(g_cvb)[tid];
    }
    if (lane < NW) stok[wid][lane] = tok[b * NW + lane];
    __syncthreads();

    for (int n = 0; n < NW; n++) {
        const int tc  = stok[wid][n];
        const int tp  = (n > 0)      ? stok[wid][n - 1] : -1;
        const int tn2 = (n < NW - 1) ? stok[wid][n + 1] : -1;
        const float4* q1 = reinterpret_cast<const float4*>(g_Q + (size_t)tc * 600 + 200);
        const float4* q0 = (tp  >= 0) ? reinterpret_cast<const float4*>(g_Q + (size_t)tp  * 600)       : nullptr;
        const float4* q2 = (tn2 >= 0) ? reinterpret_cast<const float4*>(g_Q + (size_t)tn2 * 600 + 400) : nullptr;

        float s = 0.f;
        #pragma unroll
        for (int a4 = lane; a4 < AD / 4; a4 += 32) {
            float4 h = scvb[a4];
            float4 c = q1[a4];
            h.x += c.x; h.y += c.y; h.z += c.z; h.w += c.w;
            if (q0) { float4 p = q0[a4]; h.x += p.x; h.y += p.y; h.z += p.z; h.w += p.w; }
            if (q2) { float4 p = q2[a4]; h.x += p.x; h.y += p.y; h.z += p.z; h.w += p.w; }
            float4 qq = sq[a4];
            s += ftanh(h.x) * qq.x + ftanh(h.y) * qq.y + ftanh(h.z) * qq.z + ftanh(h.w) * qq.w;
        }
        #pragma unroll
        for (int off = 16; off; off >>= 1)
            s += __shfl_down_sync(0xffffffffu, s, off);
        if (lane == 0) g_aT[n * B_SZ + b] = s;
    }
}

// ---------------- softmax stats over batch axis ----------------
__global__ __launch_bounds__(1024)
void softmax_stats_kernel()
{
    __shared__ float red[1024];
    const int n = blockIdx.x;
    const int tid = threadIdx.x;
    const float* row = g_aT + (size_t)n * B_SZ;

    float mx = -INFINITY;
    for (int b = tid; b < B_SZ; b += 1024) mx = fmaxf(mx, row[b]);
    red[tid] = mx;
    __syncthreads();
    for (int s = 512; s > 0; s >>= 1) {
        if (tid < s) red[tid] = fmaxf(red[tid], red[tid + s]);
        __syncthreads();
    }
    mx = red[0];
    __syncthreads();

    float sum = 0.f;
    for (int b = tid; b < B_SZ; b += 1024) sum += expf(row[b] - mx);
    red[tid] = sum;
    __syncthreads();
    for (int s = 512; s > 0; s >>= 1) {
        if (tid < s) red[tid] += red[tid + s];
        __syncthreads();
    }
    if (tid == 0) { g_mx[n] = mx; g_isum[n] = 1.f / red[0]; }
}

// ---------------- build G (tf32-rounded, permuted/padded layout) ----------------
__global__ __launch_bounds__(128)
void gbuild_kernel(const int* __restrict__ tok, const float* __restrict__ emb)
{
    __shared__ float sal[NW + 2];
    __shared__ int stok[NW];
    const int b = blockIdx.x;
    const int tid = threadIdx.x;

    if (tid < NW) {
        sal[tid + 1] = expf(g_aT[tid * B_SZ + b] - g_mx[tid]) * g_isum[tid];
        stok[tid] = tok[b * NW + tid];
    }
    if (tid == NW)     sal[0] = 0.f;
    if (tid == NW + 1) sal[NW + 1] = 0.f;
    __syncthreads();

    if (tid == 0) {
        float s = 0.f;
        #pragma unroll
        for (int n = 1; n <= NW; n++) s += sal[n];
        g_salpha[b] = s;
    }

    // zero the pad words (i = 300..303 in each slice)
    if (tid >= 120 && tid < 132) {
        const int j  = tid - 120;       // 0..11
        const int sl = j / 4;
        const int pw = j % 4;
        // stored positions for logical i=300..303 within block 18: pos(i&15) for 12..15
        const int pos = (12 + pw);
        const int kk  = (12 & 8) | (((12 + pw) >> 1) & 3) | (((12 + pw) & 1) << 2);
        (void)kk; (void)pos;
        // positions 9,11,13,15 hold logical 12,13,14,15 (i.e. i>=300) -> zero them
        g_GP[(size_t)b * KF_PAD + sl * KQ_PAD + 288 + 9 + pw * 2] = 0.f;
    }

    if (tid < WD / 4) {
        const int i0 = tid * 4;
        float4 g0 = make_float4(0.f, 0.f, 0.f, 0.f);
        float4 g1 = g0, g2 = g0;
        #pragma unroll
        for (int m = 0; m < NW; m++) {
            const float4 e = reinterpret_cast<const float4*>(
                emb + (size_t)stok[m] * WD)[tid];
            const float w1 = sal[m + 1];
            const float w0 = sal[m + 2];
            const float w2 = sal[m];
            g1.x += w1 * e.x; g1.y += w1 * e.y; g1.z += w1 * e.z; g1.w += w1 * e.w;
            g0.x += w0 * e.x; g0.y += w0 * e.y; g0.z += w0 * e.z; g0.w += w0 * e.w;
            g2.x += w2 * e.x; g2.y += w2 * e.y; g2.z += w2 * e.z; g2.w += w2 * e.w;
        }
        // scatter-store into k-pair permuted layout:
        // for i0 % 4 == 0: positions (i0&~15) + base2 + 2j, base2 = (i0&8) + ((i0>>2)&1)
        const int base = (i0 & ~15) + (i0 & 8) + ((i0 >> 2) & 1);
        float* gp = g_GP + (size_t)b * KF_PAD;
        float* p0 = gp + base;                       // slice 0 (g0)
        float* p1 = gp + KQ_PAD + base;              // slice 1 (g1)
        float* p2 = gp + 2 * KQ_PAD + base;          // slice 2 (g2)
        p0[0] = rtf32(g0.x); p0[2] = rtf32(g0.y); p0[4] = rtf32(g0.z); p0[6] = rtf32(g0.w);
        p1[0] = rtf32(g1.x); p1[2] = rtf32(g1.y); p1[4] = rtf32(g1.z); p1[6] = rtf32(g1.w);
        p2[0] = rtf32(g2.x); p2[2] = rtf32(g2.y); p2[4] = rtf32(g2.z); p2[6] = rtf32(g2.w);
    }
}

// ---------------- launch ----------------
extern "C" void kernel_launch(void* const* d_in, const int* in_sizes, int n_in,
                              void* d_out, int out_size)
{
    const int*   tok    = (const int*)  d_in[0];
    const float* emb    = (const float*)d_in[1];
    const float* conv_w = (const float*)d_in[2];
    const float* conv_b = (const float*)d_in[3];
    const float* v      = (const float*)d_in[4];
    const float* vb     = (const float*)d_in[5];
    const float* q      = (const float*)d_in[6];
    float* out = (float*)d_out;

    float *pembP, *pMtP, *pQ, *pGP, *pWc2tP, *psal;
    cudaGetSymbolAddress((void**)&pembP,  g_embP);
    cudaGetSymbolAddress((void**)&pMtP,   g_MtP);
    cudaGetSymbolAddress((void**)&pQ,     g_Q);
    cudaGetSymbolAddress((void**)&pGP,    g_GP);
    cudaGetSymbolAddress((void**)&pWc2tP, g_Wc2tP);
    cudaGetSymbolAddress((void**)&psal,   g_salpha);

    cudaFuncSetAttribute(tgemm_kernel<128>,
                         cudaFuncAttributeMaxDynamicSharedMemorySize, SMEM2(128));
    cudaFuncSetAttribute(tgemm_kernel<80>,
                         cudaFuncAttributeMaxDynamicSharedMemorySize, SMEM2(80));

    // 1. prep (permuted/padded tf32 operands)
    prep_embP_kernel<<<(VOCAB * KQ_PAD + 255) / 256, 256>>>(emb);
    prep_MtP_kernel<<<(NB_PAD * KQ_PAD + 255) / 256, 256>>>(conv_w, v);
    prep_cvb_kernel<<<1, 256>>>(conv_b, v, vb);
    prep_Wc2tP_kernel<<<(CH * KF_PAD + 255) / 256, 256>>>(conv_w);

    // 2. Q = embP @ MtP^T : [32000,304] x [640,304]^T -> [32000,600]
    {
        dim3 grid(5, VOCAB / 128);
        tgemm_kernel<128><<<grid, 128, SMEM2(128)>>>(pembP, pMtP, pQ, VOCAB, 600, KQ_PAD,
                                                     nullptr, nullptr);
    }

    // 3. attention scores
    score_kernel<<<B_SZ / 8, 256>>>(tok, q);

    // 4. softmax stats over batch axis
    softmax_stats_kernel<<<NW, 1024>>>();

    // 5. build G (permuted/padded) and sum-alpha
    gbuild_kernel<<<B_SZ, 128>>>(tok, emb);

    // 6. e = GP @ Wc2tP^T + salpha * conv_b : [32768,912] x [400,912]^T -> [32768,400]
    {
        dim3 grid(CH / 80, B_SZ / 128);
        tgemm_kernel<80><<<grid, 128, SMEM2(80)>>>(pGP, pWc2tP, out, B_SZ, CH, KF_PAD,
                                                   psal, conv_b);
    }
}

// round 9
// speedup vs baseline: 1.6998x; 1.6998x over previous
#include <cuda_runtime.h>
#include <math.h>
#include <stdint.h>

#define B_SZ   32768
#define NW     30
#define VOCAB  32000
#define WD     300
#define CH     400
#define AD     200

#define KQ_PAN 19      // ceil(300/16)
#define KF_PAN 57      // ceil(900/16)
#define NQ_PAD 640     // Q-gemm B rows padded (600 -> 640)

// ---------------- scratch (static device globals; no allocation) ----------------
__device__ __align__(16) float g_Mpi[KQ_PAN * 8 * 2 * NQ_PAD];   // pair-interleaved B (Q gemm)
__device__ __align__(16) float g_cvb[AD];
__device__ __align__(16) float g_Q[VOCAB * 600];                 // [tok][k*200+a]
__device__ __align__(16) float g_aT[NW * B_SZ];
__device__ float g_mx[NW];
__device__ float g_isum[NW];
__device__ float g_pm[NW * 8];
__device__ float g_ps[NW * 8];
__device__ __align__(16) float g_G[(size_t)B_SZ * 900];          // tf32-rounded [b][k*300+i]
__device__ float g_salpha[B_SZ];
__device__ __align__(16) float g_Wpi[KF_PAN * 8 * 2 * CH];       // pair-interleaved B (final)
__device__ __align__(16) float g_embT[VOCAB * WD];               // tf32-rounded emb copy

__device__ __forceinline__ uint32_t f2tf32(float x)
{
    uint32_t r;
    asm("cvt.rna.tf32.f32 %0, %1;" : "=r"(r) : "f"(x));
    return r;
}
__device__ __forceinline__ float rtf32(float x) { return __uint_as_float(f2tf32(x)); }

__device__ __forceinline__ float ftanh(float x)
{
    float e = __expf(2.f * x);
    return 1.f - __fdividef(2.f, e + 1.f);
}

// ---------------- prep kernels ----------------
// pair-interleaved B for Q gemm: element (k, n) of M[k=i][n=ks*200+a] stored at
// [panel=k/16][p = 4*((k%16)/8) + (k%4)][2n + ((k%8)/4)]
__global__ void prep_Mpi_kernel(const float* __restrict__ conv_w, const float* __restrict__ v)
{
    int idx = blockIdx.x * blockDim.x + threadIdx.x;
    if (idx >= KQ_PAN * 8 * 2 * NQ_PAD) return;
    const int pan = idx / (8 * 2 * NQ_PAD);
    const int rem = idx % (8 * 2 * NQ_PAD);
    const int p   = rem / (2 * NQ_PAD);
    const int c   = rem % (2 * NQ_PAD);
    const int n   = c >> 1;
    const int j   = c & 1;
    const int k   = pan * 16 + ((p >> 2) << 3) + (p & 3) + j * 4;   // logical K index (= i)
    float val = 0.f;
    if (k < WD && n < 600) {
        const int ks = n / 200;
        const int a  = n % 200;
        float s = 0.f;
        #pragma unroll 4
        for (int o = 0; o < CH; o++)
            s += conv_w[o * (WD * 3) + k * 3 + ks] * v[o * AD + a];
        val = rtf32(s);
    }
    g_Mpi[idx] = val;
}

// pair-interleaved B for final gemm: element (k, n=o) of Wc2[k = sl*300+i][o]
__global__ void prep_Wpi_kernel(const float* __restrict__ conv_w)
{
    int idx = blockIdx.x * blockDim.x + threadIdx.x;
    if (idx >= KF_PAN * 8 * 2 * CH) return;
    const int pan = idx / (8 * 2 * CH);
    const int rem = idx % (8 * 2 * CH);
    const int p   = rem / (2 * CH);
    const int c   = rem % (2 * CH);
    const int n   = c >> 1;
    const int j   = c & 1;
    const int k   = pan * 16 + ((p >> 2) << 3) + (p & 3) + j * 4;
    float val = 0.f;
    if (k < 900) {
        const int sl = k / WD;
        const int i  = k % WD;
        val = rtf32(conv_w[n * 900 + i * 3 + sl]);
    }
    g_Wpi[idx] = val;
}

__global__ void prep_cvb_kernel(const float* __restrict__ conv_b,
                                const float* __restrict__ v,
                                const float* __restrict__ vb)
{
    int a = blockIdx.x * blockDim.x + threadIdx.x;
    if (a >= AD) return;
    float s = vb[a];
    for (int o = 0; o < CH; o++) s += conv_b[o] * v[o * AD + a];
    g_cvb[a] = s;
}

__global__ void round_emb_kernel(const float* __restrict__ emb)
{
    int idx = blockIdx.x * blockDim.x + threadIdx.x;
    const int n4 = VOCAB * WD / 4;
    if (idx >= n4) return;
    float4 v = reinterpret_cast<const float4*>(emb)[idx];
    v.x = rtf32(v.x); v.y = rtf32(v.y); v.z = rtf32(v.z); v.w = rtf32(v.w);
    reinterpret_cast<float4*>(g_embT)[idx] = v;
}

// ---------------- tf32 mma.sync GEMM, pair-interleaved B, cp.async 4-stage -----
// C[M,N] = A[M,K] @ Bpi (+ rs[m]*bias[n]); A plain [M][K] tf32 bits (K clamped),
// Bpi pair-interleaved [K/16][8][2*NP] tf32 bits (zero-padded).
// Block 128 x BN, 128 threads (4 warps 2x2), warp tile 64 x BN/2. M mult of 128.

__device__ __forceinline__ void mma_tf32(float* c,
                                         uint32_t a0, uint32_t a1, uint32_t a2, uint32_t a3,
                                         uint32_t b0, uint32_t b1)
{
    asm volatile(
        "mma.sync.aligned.m16n8k8.row.col.f32.tf32.tf32.f32 "
        "{%0,%1,%2,%3}, {%4,%5,%6,%7}, {%8,%9}, {%0,%1,%2,%3};\n"
        : "+f"(c[0]), "+f"(c[1]), "+f"(c[2]), "+f"(c[3])
        : "r"(a0), "r"(a1), "r"(a2), "r"(a3), "r"(b0), "r"(b1));
}

__device__ __forceinline__ void cp16z(uint32_t dst, const void* src, int bytes)
{
    asm volatile("cp.async.cg.shared.global [%0], [%1], 16, %2;\n"
                 :: "r"(dst), "l"(src), "r"(bytes));
}
__device__ __forceinline__ void cp16(uint32_t dst, const void* src)
{
    asm volatile("cp.async.cg.shared.global [%0], [%1], 16;\n"
                 :: "r"(dst), "l"(src));
}

#define STAGES 4
#define AS_W 20                 // 16 k + 4 pad

template<int BN>
__global__ __launch_bounds__(128, (BN == 80) ? 3 : 2)
void tgemm_kernel(const float* __restrict__ A, const float* __restrict__ Bpi,
                  float* __restrict__ C, int M, int N, int K, int NP,
                  const float* __restrict__ rs, const float* __restrict__ bias)
{
    constexpr int BP_W  = 2 * BN + 8;            // smem words per pair-row
    constexpr int BCH   = 8 * (2 * BN) / 4;      // 16B chunks per B panel
    constexpr int BRND  = (BCH + 127) / 128;
    constexpr int NT    = BN / 16;

    extern __shared__ __align__(16) uint32_t smem[];
    uint32_t* Asm = smem;                            // [STAGES][128][AS_W]
    uint32_t* Bsm = smem + STAGES * 128 * AS_W;      // [STAGES][8][BP_W]
    const uint32_t as_base = (uint32_t)__cvta_generic_to_shared(Asm);
    const uint32_t bs_base = (uint32_t)__cvta_generic_to_shared(Bsm);

    const int tid    = threadIdx.x;
    const int lane   = tid & 31;
    const int warp   = tid >> 5;
    const int warp_m = warp & 1;
    const int warp_n = warp >> 1;
    const int m0 = blockIdx.y * 128;
    const int n0 = blockIdx.x * BN;

    const int am = tid >> 2;          // 0..31
    const int ak = (tid & 3) * 4;     // 0,4,8,12

    const int nIter = (K + 15) / 16;

    float acc[4][NT][4];
    #pragma unroll
    for (int mt = 0; mt < 4; mt++)
        #pragma unroll
        for (int nt = 0; nt < NT; nt++)
            #pragma unroll
            for (int i = 0; i < 4; i++) acc[mt][nt][i] = 0.f;

    auto issue_panel = [&](int pnl) {
        const int s   = pnl & (STAGES - 1);
        const int kk0 = pnl * 16;
        // A: 128 rows x 4 chunks of 16B (K-clamped, zero-filled)
        #pragma unroll
        for (int r = 0; r < 4; r++) {
            const int m  = am + r * 32;
            const int kg = kk0 + ak;
            int bytes = (K - kg) * 4;
            bytes = bytes < 0 ? 0 : (bytes > 16 ? 16 : bytes);
            const float* src = A + (size_t)(m0 + m) * K + (kg < K ? kg : 0);
            cp16z(as_base + (((s * 128 + m) * AS_W) + ak) * 4, src, bytes);
        }
        // B: pair-interleaved panel, 8 rows x 2*BN words (always fully valid:
        // Bpi is pre-padded in K and NP is a multiple of BN)
        const float* bsrc0 = Bpi + ((size_t)pnl * 8) * (2 * NP) + 2 * n0;
        #pragma unroll
        for (int r = 0; r < BRND; r++) {
            const int idx = tid + r * 128;
            if (BCH % 128 == 0 || idx < BCH) {
                const int p  = idx / (2 * BN / 4);
                const int ch = idx % (2 * BN / 4);
                const float* src = bsrc0 + (size_t)p * (2 * NP) + ch * 4;
                cp16(bs_base + (((s * 8 + p) * BP_W) + ch * 4) * 4, src);
            }
        }
        asm volatile("cp.async.commit_group;\n");
    };

    issue_panel(0);
    issue_panel(1);
    issue_panel(2);

    for (int it = 0; it < nIter; ++it) {
        asm volatile("cp.async.wait_group %0;\n" :: "n"(STAGES - 2));
        __syncthreads();

        const int s = it & (STAGES - 1);
        const uint32_t* Asb = Asm + s * 128 * AS_W;
        const uint32_t* Bsb = Bsm + s * 8 * BP_W;

        #pragma unroll
        for (int ks = 0; ks < 2; ks++) {
            const int kb = ks * 8 + (lane & 3);
            const int pr = ks * 4 + (lane & 3);      // pair-row
            uint32_t af[4][4];
            uint32_t bf[NT][2];
            #pragma unroll
            for (int mt = 0; mt < 4; mt++) {
                const int rb = warp_m * 64 + mt * 16 + (lane >> 2);
                af[mt][0] = Asb[rb * AS_W + kb];
                af[mt][1] = Asb[(rb + 8) * AS_W + kb];
                af[mt][2] = Asb[rb * AS_W + kb + 4];
                af[mt][3] = Asb[(rb + 8) * AS_W + kb + 4];
            }
            #pragma unroll
            for (int nt = 0; nt < NT; nt++) {
                const int nc = warp_n * (BN / 2) + nt * 8 + (lane >> 2);
                uint2 bv = *reinterpret_cast<const uint2*>(&Bsb[pr * BP_W + nc * 2]);
                bf[nt][0] = bv.x;
                bf[nt][1] = bv.y;
            }
            #pragma unroll
            for (int mt = 0; mt < 4; mt++)
                #pragma unroll
                for (int nt = 0; nt < NT; nt++)
                    mma_tf32(acc[mt][nt], af[mt][0], af[mt][1], af[mt][2], af[mt][3],
                             bf[nt][0], bf[nt][1]);
        }

        if (it + STAGES - 1 < nIter) {
            issue_panel(it + STAGES - 1);
        } else {
            asm volatile("cp.async.commit_group;\n");
        }
    }

    // ---- epilogue ----
    #pragma unroll
    for (int mt = 0; mt < 4; mt++) {
        const int row0 = m0 + warp_m * 64 + mt * 16 + (lane >> 2);
        const int row1 = row0 + 8;
        const float r0 = rs ? rs[row0] : 0.f;
        const float r1 = rs ? rs[row1] : 0.f;
        #pragma unroll
        for (int nt = 0; nt < NT; nt++) {
            const int col = n0 + warp_n * (BN / 2) + nt * 8 + (lane & 3) * 2;
            if (col < N) {
                float v0 = acc[mt][nt][0], v1 = acc[mt][nt][1];
                float v2 = acc[mt][nt][2], v3 = acc[mt][nt][3];
                if (bias) {
                    const float b0 = bias[col], b1 = bias[col + 1];
                    v0 += r0 * b0; v1 += r0 * b1;
                    v2 += r1 * b0; v3 += r1 * b1;
                }
                *reinterpret_cast<float2*>(C + (size_t)row0 * N + col) = make_float2(v0, v1);
                *reinterpret_cast<float2*>(C + (size_t)row1 * N + col) = make_float2(v2, v3);
            }
        }
    }
}

#define SMEM3(BN) (STAGES * (128 * AS_W + 8 * (2 * (BN) + 8)) * 4)

// ---------------- scores ----------------
__global__ __launch_bounds__(256)
void score_kernel(const int* __restrict__ tok, const float* __restrict__ qv)
{
    __shared__ float4 sq[AD / 4];
    __shared__ float4 scvb[AD / 4];
    __shared__ int stok[8][NW];

    const int tid = threadIdx.x;
    const int wid = tid >> 5;
    const int lane = tid & 31;
    const int b = blockIdx.x * 8 + wid;

    if (tid < AD / 4) {
        sq[tid]   = reinterpret_cast<const float4*>(qv)[tid];
        scvb[tid] = reinterpret_cast<const float4*>(g_cvb)[tid];
    }
    if (lane < NW) stok[wid][lane] = tok[b * NW + lane];
    __syncthreads();

    for (int n = 0; n < NW; n++) {
        const int tc  = stok[wid][n];
        const int tp  = (n > 0)      ? stok[wid][n - 1] : -1;
        const int tn2 = (n < NW - 1) ? stok[wid][n + 1] : -1;
        const float4* q1 = reinterpret_cast<const float4*>(g_Q + (size_t)tc * 600 + 200);
        const float4* q0 = (tp  >= 0) ? reinterpret_cast<const float4*>(g_Q + (size_t)tp  * 600)       : nullptr;
        const float4* q2 = (tn2 >= 0) ? reinterpret_cast<const float4*>(g_Q + (size_t)tn2 * 600 + 400) : nullptr;

        float s = 0.f;
        #pragma unroll
        for (int a4 = lane; a4 < AD / 4; a4 += 32) {
            float4 h = scvb[a4];
            float4 c = q1[a4];
            h.x += c.x; h.y += c.y; h.z += c.z; h.w += c.w;
            if (q0) { float4 p = q0[a4]; h.x += p.x; h.y += p.y; h.z += p.z; h.w += p.w; }
            if (q2) { float4 p = q2[a4]; h.x += p.x; h.y += p.y; h.z += p.z; h.w += p.w; }
            float4 qq = sq[a4];
            s += ftanh(h.x) * qq.x + ftanh(h.y) * qq.y + ftanh(h.z) * qq.z + ftanh(h.w) * qq.w;
        }
        #pragma unroll
        for (int off = 16; off; off >>= 1)
            s += __shfl_down_sync(0xffffffffu, s, off);
        if (lane == 0) g_aT[n * B_SZ + b] = s;
    }
}

// ---------------- two-stage softmax stats over batch axis ----------------
__global__ __launch_bounds__(512)
void softmax_part_kernel()
{
    __shared__ float red[512];
    const int n = blockIdx.x;
    const int c = blockIdx.y;
    const int tid = threadIdx.x;
    const float* row = g_aT + (size_t)n * B_SZ + c * 4096;

    float mx = -INFINITY;
    #pragma unroll
    for (int i = 0; i < 8; i++) mx = fmaxf(mx, row[tid + i * 512]);
    red[tid] = mx;
    __syncthreads();
    for (int s = 256; s > 0; s >>= 1) {
        if (tid < s) red[tid] = fmaxf(red[tid], red[tid + s]);
        __syncthreads();
    }
    mx = red[0];
    __syncthreads();

    float sum = 0.f;
    #pragma unroll
    for (int i = 0; i < 8; i++) sum += __expf(row[tid + i * 512] - mx);
    red[tid] = sum;
    __syncthreads();
    for (int s = 256; s > 0; s >>= 1) {
        if (tid < s) red[tid] += red[tid + s];
        __syncthreads();
    }
    if (tid == 0) { g_pm[n * 8 + c] = mx; g_ps[n * 8 + c] = red[0]; }
}

__global__ void softmax_comb_kernel()
{
    const int n = threadIdx.x;
    if (n >= NW) return;
    float M = -INFINITY;
    #pragma unroll
    for (int c = 0; c < 8; c++) M = fmaxf(M, g_pm[n * 8 + c]);
    float S = 0.f;
    #pragma unroll
    for (int c = 0; c < 8; c++) S += g_ps[n * 8 + c] * __expf(g_pm[n * 8 + c] - M);
    g_mx[n] = M;
    g_isum[n] = 1.f / S;
}

// ---------------- build G (tf32-rounded) ----------------
__global__ __launch_bounds__(128)
void gbuild_kernel(const int* __restrict__ tok, const float* __restrict__ emb)
{
    __shared__ float sal[NW + 2];
    __shared__ int stok[NW];
    const int b = blockIdx.x;
    const int tid = threadIdx.x;

    if (tid < NW) {
        sal[tid + 1] = expf(g_aT[tid * B_SZ + b] - g_mx[tid]) * g_isum[tid];
        stok[tid] = tok[b * NW + tid];
    }
    if (tid == NW)     sal[0] = 0.f;
    if (tid == NW + 1) sal[NW + 1] = 0.f;
    __syncthreads();

    if (tid == 0) {
        float s = 0.f;
        #pragma unroll
        for (int n = 1; n <= NW; n++) s += sal[n];
        g_salpha[b] = s;
    }

    if (tid < WD / 4) {
        float4 g0 = make_float4(0.f, 0.f, 0.f, 0.f);
        float4 g1 = g0, g2 = g0;
        #pragma unroll
        for (int m = 0; m < NW; m++) {
            const float4 e = reinterpret_cast<const float4*>(
                emb + (size_t)stok[m] * WD)[tid];
            const float w1 = sal[m + 1];
            const float w0 = sal[m + 2];
            const float w2 = sal[m];
            g1.x += w1 * e.x; g1.y += w1 * e.y; g1.z += w1 * e.z; g1.w += w1 * e.w;
            g0.x += w0 * e.x; g0.y += w0 * e.y; g0.z += w0 * e.z; g0.w += w0 * e.w;
            g2.x += w2 * e.x; g2.y += w2 * e.y; g2.z += w2 * e.z; g2.w += w2 * e.w;
        }
        g0.x = rtf32(g0.x); g0.y = rtf32(g0.y); g0.z = rtf32(g0.z); g0.w = rtf32(g0.w);
        g1.x = rtf32(g1.x); g1.y = rtf32(g1.y); g1.z = rtf32(g1.z); g1.w = rtf32(g1.w);
        g2.x = rtf32(g2.x); g2.y = rtf32(g2.y); g2.z = rtf32(g2.z); g2.w = rtf32(g2.w);
        float4* gp = reinterpret_cast<float4*>(g_G + (size_t)b * 900);
        gp[tid]            = g0;
        gp[WD / 4 + tid]   = g1;
        gp[WD / 2 + tid]   = g2;
    }
}

// ---------------- launch ----------------
extern "C" void kernel_launch(void* const* d_in, const int* in_sizes, int n_in,
                              void* d_out, int out_size)
{
    const int*   tok    = (const int*)  d_in[0];
    const float* emb    = (const float*)d_in[1];
    const float* conv_w = (const float*)d_in[2];
    const float* conv_b = (const float*)d_in[3];
    const float* v      = (const float*)d_in[4];
    const float* vb     = (const float*)d_in[5];
    const float* q      = (const float*)d_in[6];
    float* out = (float*)d_out;

    float *pMpi, *pQ, *pG, *pWpi, *psal, *pembT;
    cudaGetSymbolAddress((void**)&pMpi,  g_Mpi);
    cudaGetSymbolAddress((void**)&pQ,    g_Q);
    cudaGetSymbolAddress((void**)&pG,    g_G);
    cudaGetSymbolAddress((void**)&pWpi,  g_Wpi);
    cudaGetSymbolAddress((void**)&psal,  g_salpha);
    cudaGetSymbolAddress((void**)&pembT, g_embT);

    cudaFuncSetAttribute(tgemm_kernel<128>,
                         cudaFuncAttributeMaxDynamicSharedMemorySize, SMEM3(128));
    cudaFuncSetAttribute(tgemm_kernel<80>,
                         cudaFuncAttributeMaxDynamicSharedMemorySize, SMEM3(80));

    // 1. prep (pair-interleaved B operands) + tf32-rounded emb copy
    prep_Mpi_kernel<<<(KQ_PAN * 8 * 2 * NQ_PAD + 255) / 256, 256>>>(conv_w, v);
    prep_cvb_kernel<<<1, 256>>>(conv_b, v, vb);
    prep_Wpi_kernel<<<(KF_PAN * 8 * 2 * CH + 255) / 256, 256>>>(conv_w);
    round_emb_kernel<<<(VOCAB * WD / 4 + 255) / 256, 256>>>(emb);

    // 2. Q = embT @ M : [32000,300] x [300,600]  (pair-interleaved B, NP=640)
    {
        dim3 grid(5, VOCAB / 128);
        tgemm_kernel<128><<<grid, 128, SMEM3(128)>>>(pembT, pMpi, pQ, VOCAB, 600, WD,
                                                     NQ_PAD, nullptr, nullptr);
    }

    // 3. attention scores
    score_kernel<<<B_SZ / 8, 256>>>(tok, q);

    // 4. softmax stats (two-stage)
    {
        dim3 pgrid(NW, 8);
        softmax_part_kernel<<<pgrid, 512>>>();
        softmax_comb_kernel<<<1, 32>>>();
    }

    // 5. build G (tf32-rounded) and sum-alpha
    gbuild_kernel<<<B_SZ, 128>>>(tok, emb);

    // 6. e = G @ Wc2 + salpha * conv_b : [32768,900] x [900,400]  (NP=400, BN=80)
    {
        dim3 grid(CH / 80, B_SZ / 128);
        tgemm_kernel<80><<<grid, 128, SMEM3(80)>>>(pG, pWpi, out, B_SZ, CH, 900,
                                                   CH, psal, conv_b);
    }
}

// round 10
// speedup vs baseline: 1.7064x; 1.0039x over previous
#include <cuda_runtime.h>
#include <math.h>
#include <stdint.h>

#define B_SZ   32768
#define NW     30
#define VOCAB  32000
#define WD     300
#define CH     400
#define AD     200

#define KQ_PAN 19      // ceil(300/16)
#define KF_PAN 57      // ceil(900/16)
#define NQ_PAD 640     // Q-gemm B rows padded (600 -> 640), multiple of 80

// ---------------- scratch (static device globals; no allocation) ----------------
__device__ __align__(16) float g_Mpi[KQ_PAN * 8 * 2 * NQ_PAD];   // pair-interleaved B (Q gemm)
__device__ __align__(16) float g_cvb[AD];
__device__ __align__(16) float g_Q[VOCAB * 600];                 // [tok][k*200+a]
__device__ __align__(16) float g_aT[NW * B_SZ];
__device__ float g_mx[NW];
__device__ float g_isum[NW];
__device__ float g_pm[NW * 8];
__device__ float g_ps[NW * 8];
__device__ __align__(16) float g_G[(size_t)B_SZ * 900];          // tf32-rounded [b][k*300+i]
__device__ float g_salpha[B_SZ];
__device__ __align__(16) float g_Wpi[KF_PAN * 8 * 2 * CH];       // pair-interleaved B (final)
__device__ __align__(16) float g_embT[VOCAB * WD];               // tf32-rounded emb copy

__device__ __forceinline__ uint32_t f2tf32(float x)
{
    uint32_t r;
    asm("cvt.rna.tf32.f32 %0, %1;" : "=r"(r) : "f"(x));
    return r;
}
__device__ __forceinline__ float rtf32(float x) { return __uint_as_float(f2tf32(x)); }

__device__ __forceinline__ float ftanh(float x)
{
    float e = __expf(2.f * x);
    return 1.f - __fdividef(2.f, e + 1.f);
}

// ---------------- prep kernels ----------------
// pair-interleaved B for Q gemm: element (k, n) of M[k=i][n=ks*200+a] stored at
// [panel=k/16][p = 4*((k%16)/8) + (k%4)][2n + ((k%8)/4)]
__global__ void prep_Mpi_kernel(const float* __restrict__ conv_w, const float* __restrict__ v)
{
    int idx = blockIdx.x * blockDim.x + threadIdx.x;
    if (idx >= KQ_PAN * 8 * 2 * NQ_PAD) return;
    const int pan = idx / (8 * 2 * NQ_PAD);
    const int rem = idx % (8 * 2 * NQ_PAD);
    const int p   = rem / (2 * NQ_PAD);
    const int c   = rem % (2 * NQ_PAD);
    const int n   = c >> 1;
    const int j   = c & 1;
    const int k   = pan * 16 + ((p >> 2) << 3) + (p & 3) + j * 4;   // logical K index (= i)
    float val = 0.f;
    if (k < WD && n < 600) {
        const int ks = n / 200;
        const int a  = n % 200;
        float s = 0.f;
        #pragma unroll 4
        for (int o = 0; o < CH; o++)
            s += conv_w[o * (WD * 3) + k * 3 + ks] * v[o * AD + a];
        val = rtf32(s);
    }
    g_Mpi[idx] = val;
}

// pair-interleaved B for final gemm: element (k, n=o) of Wc2[k = sl*300+i][o]
__global__ void prep_Wpi_kernel(const float* __restrict__ conv_w)
{
    int idx = blockIdx.x * blockDim.x + threadIdx.x;
    if (idx >= KF_PAN * 8 * 2 * CH) return;
    const int pan = idx / (8 * 2 * CH);
    const int rem = idx % (8 * 2 * CH);
    const int p   = rem / (2 * CH);
    const int c   = rem % (2 * CH);
    const int n   = c >> 1;
    const int j   = c & 1;
    const int k   = pan * 16 + ((p >> 2) << 3) + (p & 3) + j * 4;
    float val = 0.f;
    if (k < 900) {
        const int sl = k / WD;
        const int i  = k % WD;
        val = rtf32(conv_w[n * 900 + i * 3 + sl]);
    }
    g_Wpi[idx] = val;
}

__global__ void prep_cvb_kernel(const float* __restrict__ conv_b,
                                const float* __restrict__ v,
                                const float* __restrict__ vb)
{
    int a = blockIdx.x * blockDim.x + threadIdx.x;
    if (a >= AD) return;
    float s = vb[a];
    for (int o = 0; o < CH; o++) s += conv_b[o] * v[o * AD + a];
    g_cvb[a] = s;
}

__global__ void round_emb_kernel(const float* __restrict__ emb)
{
    int idx = blockIdx.x * blockDim.x + threadIdx.x;
    const int n4 = VOCAB * WD / 4;
    if (idx >= n4) return;
    float4 v = reinterpret_cast<const float4*>(emb)[idx];
    v.x = rtf32(v.x); v.y = rtf32(v.y); v.z = rtf32(v.z); v.w = rtf32(v.w);
    reinterpret_cast<float4*>(g_embT)[idx] = v;
}

// ---------------- tf32 mma.sync GEMM, pair-interleaved B, cp.async 4-stage -----
// C[M,N] = A[M,K] @ Bpi (+ rs[m]*bias[n]); A plain [M][K] tf32 bits (K clamped),
// Bpi pair-interleaved [K/16][8][2*NP] tf32 bits (zero-padded).
// Block 128 x BN, 128 threads (4 warps 2x2), warp tile 64 x BN/2. M mult of 128.

__device__ __forceinline__ void mma_tf32(float* c,
                                         uint32_t a0, uint32_t a1, uint32_t a2, uint32_t a3,
                                         uint32_t b0, uint32_t b1)
{
    asm volatile(
        "mma.sync.aligned.m16n8k8.row.col.f32.tf32.tf32.f32 "
        "{%0,%1,%2,%3}, {%4,%5,%6,%7}, {%8,%9}, {%0,%1,%2,%3};\n"
        : "+f"(c[0]), "+f"(c[1]), "+f"(c[2]), "+f"(c[3])
        : "r"(a0), "r"(a1), "r"(a2), "r"(a3), "r"(b0), "r"(b1));
}

__device__ __forceinline__ void cp16z(uint32_t dst, const void* src, int bytes)
{
    asm volatile("cp.async.cg.shared.global [%0], [%1], 16, %2;\n"
                 :: "r"(dst), "l"(src), "r"(bytes));
}
__device__ __forceinline__ void cp16(uint32_t dst, const void* src)
{
    asm volatile("cp.async.cg.shared.global [%0], [%1], 16;\n"
                 :: "r"(dst), "l"(src));
}

#define STAGES 4
#define AS_W 20                 // 16 k + 4 pad

template<int BN>
__global__ __launch_bounds__(128, (BN == 80) ? 3 : 2)
void tgemm_kernel(const float* __restrict__ A, const float* __restrict__ Bpi,
                  float* __restrict__ C, int M, int N, int K, int NP,
                  const float* __restrict__ rs, const float* __restrict__ bias)
{
    constexpr int BP_W  = 2 * BN + 8;            // smem words per pair-row
    constexpr int BCH   = 8 * (2 * BN) / 4;      // 16B chunks per B panel
    constexpr int BRND  = (BCH + 127) / 128;
    constexpr int NT    = BN / 16;

    extern __shared__ __align__(16) uint32_t smem[];
    uint32_t* Asm = smem;                            // [STAGES][128][AS_W]
    uint32_t* Bsm = smem + STAGES * 128 * AS_W;      // [STAGES][8][BP_W]
    const uint32_t as_base = (uint32_t)__cvta_generic_to_shared(Asm);
    const uint32_t bs_base = (uint32_t)__cvta_generic_to_shared(Bsm);

    const int tid    = threadIdx.x;
    const int lane   = tid & 31;
    const int warp   = tid >> 5;
    const int warp_m = warp & 1;
    const int warp_n = warp >> 1;
    const int m0 = blockIdx.y * 128;
    const int n0 = blockIdx.x * BN;

    const int am = tid >> 2;          // 0..31
    const int ak = (tid & 3) * 4;     // 0,4,8,12

    const int nIter = (K + 15) / 16;

    float acc[4][NT][4];
    #pragma unroll
    for (int mt = 0; mt < 4; mt++)
        #pragma unroll
        for (int nt = 0; nt < NT; nt++)
            #pragma unroll
            for (int i = 0; i < 4; i++) acc[mt][nt][i] = 0.f;

    auto issue_panel = [&](int pnl) {
        const int s   = pnl & (STAGES - 1);
        const int kk0 = pnl * 16;
        // A: 128 rows x 4 chunks of 16B (K-clamped, zero-filled)
        #pragma unroll
        for (int r = 0; r < 4; r++) {
            const int m  = am + r * 32;
            const int kg = kk0 + ak;
            int bytes = (K - kg) * 4;
            bytes = bytes < 0 ? 0 : (bytes > 16 ? 16 : bytes);
            const float* src = A + (size_t)(m0 + m) * K + (kg < K ? kg : 0);
            cp16z(as_base + (((s * 128 + m) * AS_W) + ak) * 4, src, bytes);
        }
        // B: pair-interleaved panel, 8 rows x 2*BN words (pre-padded; always valid)
        const float* bsrc0 = Bpi + ((size_t)pnl * 8) * (2 * NP) + 2 * n0;
        #pragma unroll
        for (int r = 0; r < BRND; r++) {
            const int idx = tid + r * 128;
            if (BCH % 128 == 0 || idx < BCH) {
                const int p  = idx / (2 * BN / 4);
                const int ch = idx % (2 * BN / 4);
                const float* src = bsrc0 + (size_t)p * (2 * NP) + ch * 4;
                cp16(bs_base + (((s * 8 + p) * BP_W) + ch * 4) * 4, src);
            }
        }
        asm volatile("cp.async.commit_group;\n");
    };

    issue_panel(0);
    issue_panel(1);
    issue_panel(2);

    for (int it = 0; it < nIter; ++it) {
        asm volatile("cp.async.wait_group %0;\n" :: "n"(STAGES - 2));
        __syncthreads();

        const int s = it & (STAGES - 1);
        const uint32_t* Asb = Asm + s * 128 * AS_W;
        const uint32_t* Bsb = Bsm + s * 8 * BP_W;

        #pragma unroll
        for (int ks = 0; ks < 2; ks++) {
            const int kb = ks * 8 + (lane & 3);
            const int pr = ks * 4 + (lane & 3);      // pair-row
            uint32_t af[4][4];
            uint32_t bf[NT][2];
            #pragma unroll
            for (int mt = 0; mt < 4; mt++) {
                const int rb = warp_m * 64 + mt * 16 + (lane >> 2);
                af[mt][0] = Asb[rb * AS_W + kb];
                af[mt][1] = Asb[(rb + 8) * AS_W + kb];
                af[mt][2] = Asb[rb * AS_W + kb + 4];
                af[mt][3] = Asb[(rb + 8) * AS_W + kb + 4];
            }
            #pragma unroll
            for (int nt = 0; nt < NT; nt++) {
                const int nc = warp_n * (BN / 2) + nt * 8 + (lane >> 2);
                uint2 bv = *reinterpret_cast<const uint2*>(&Bsb[pr * BP_W + nc * 2]);
                bf[nt][0] = bv.x;
                bf[nt][1] = bv.y;
            }
            #pragma unroll
            for (int mt = 0; mt < 4; mt++)
                #pragma unroll
                for (int nt = 0; nt < NT; nt++)
                    mma_tf32(acc[mt][nt], af[mt][0], af[mt][1], af[mt][2], af[mt][3],
                             bf[nt][0], bf[nt][1]);
        }

        if (it + STAGES - 1 < nIter) {
            issue_panel(it + STAGES - 1);
        } else {
            asm volatile("cp.async.commit_group;\n");
        }
    }

    // ---- epilogue ----
    #pragma unroll
    for (int mt = 0; mt < 4; mt++) {
        const int row0 = m0 + warp_m * 64 + mt * 16 + (lane >> 2);
        const int row1 = row0 + 8;
        const float r0 = rs ? rs[row0] : 0.f;
        const float r1 = rs ? rs[row1] : 0.f;
        #pragma unroll
        for (int nt = 0; nt < NT; nt++) {
            const int col = n0 + warp_n * (BN / 2) + nt * 8 + (lane & 3) * 2;
            if (col < N) {
                float v0 = acc[mt][nt][0], v1 = acc[mt][nt][1];
                float v2 = acc[mt][nt][2], v3 = acc[mt][nt][3];
                if (bias) {
                    const float b0 = bias[col], b1 = bias[col + 1];
                    v0 += r0 * b0; v1 += r0 * b1;
                    v2 += r1 * b0; v3 += r1 * b1;
                }
                *reinterpret_cast<float2*>(C + (size_t)row0 * N + col) = make_float2(v0, v1);
                *reinterpret_cast<float2*>(C + (size_t)row1 * N + col) = make_float2(v2, v3);
            }
        }
    }
}

#define SMEM3(BN) (STAGES * (128 * AS_W + 8 * (2 * (BN) + 8)) * 4)

// ---------------- scores ----------------
__global__ __launch_bounds__(256)
void score_kernel(const int* __restrict__ tok, const float* __restrict__ qv)
{
    __shared__ float4 sq[AD / 4];
    __shared__ float4 scvb[AD / 4];
    __shared__ int stok[8][NW];

    const int tid = threadIdx.x;
    const int wid = tid >> 5;
    const int lane = tid & 31;
    const int b = blockIdx.x * 8 + wid;

    if (tid < AD / 4) {
        sq[tid]   = reinterpret_cast<const float4*>(qv)[tid];
        scvb[tid] = reinterpret_cast<const float4*>(g_cvb)[tid];
    }
    if (lane < NW) stok[wid][lane] = tok[b * NW + lane];
    __syncthreads();

    for (int n = 0; n < NW; n++) {
        const int tc  = stok[wid][n];
        const int tp  = (n > 0)      ? stok[wid][n - 1] : -1;
        const int tn2 = (n < NW - 1) ? stok[wid][n + 1] : -1;
        const float4* q1 = reinterpret_cast<const float4*>(g_Q + (size_t)tc * 600 + 200);
        const float4* q0 = (tp  >= 0) ? reinterpret_cast<const float4*>(g_Q + (size_t)tp  * 600)       : nullptr;
        const float4* q2 = (tn2 >= 0) ? reinterpret_cast<const float4*>(g_Q + (size_t)tn2 * 600 + 400) : nullptr;

        float s = 0.f;
        #pragma unroll
        for (int a4 = lane; a4 < AD / 4; a4 += 32) {
            float4 h = scvb[a4];
            float4 c = q1[a4];
            h.x += c.x; h.y += c.y; h.z += c.z; h.w += c.w;
            if (q0) { float4 p = q0[a4]; h.x += p.x; h.y += p.y; h.z += p.z; h.w += p.w; }
            if (q2) { float4 p = q2[a4]; h.x += p.x; h.y += p.y; h.z += p.z; h.w += p.w; }
            float4 qq = sq[a4];
            s += ftanh(h.x) * qq.x + ftanh(h.y) * qq.y + ftanh(h.z) * qq.z + ftanh(h.w) * qq.w;
        }
        #pragma unroll
        for (int off = 16; off; off >>= 1)
            s += __shfl_down_sync(0xffffffffu, s, off);
        if (lane == 0) g_aT[n * B_SZ + b] = s;
    }
}

// ---------------- two-stage softmax stats over batch axis ----------------
__global__ __launch_bounds__(512)
void softmax_part_kernel()
{
    __shared__ float red[512];
    const int n = blockIdx.x;
    const int c = blockIdx.y;
    const int tid = threadIdx.x;
    const float* row = g_aT + (size_t)n * B_SZ + c * 4096;

    float mx = -INFINITY;
    #pragma unroll
    for (int i = 0; i < 8; i++) mx = fmaxf(mx, row[tid + i * 512]);
    red[tid] = mx;
    __syncthreads();
    for (int s = 256; s > 0; s >>= 1) {
        if (tid < s) red[tid] = fmaxf(red[tid], red[tid + s]);
        __syncthreads();
    }
    mx = red[0];
    __syncthreads();

    float sum = 0.f;
    #pragma unroll
    for (int i = 0; i < 8; i++) sum += __expf(row[tid + i * 512] - mx);
    red[tid] = sum;
    __syncthreads();
    for (int s = 256; s > 0; s >>= 1) {
        if (tid < s) red[tid] += red[tid + s];
        __syncthreads();
    }
    if (tid == 0) { g_pm[n * 8 + c] = mx; g_ps[n * 8 + c] = red[0]; }
}

__global__ void softmax_comb_kernel()
{
    const int n = threadIdx.x;
    if (n >= NW) return;
    float M = -INFINITY;
    #pragma unroll
    for (int c = 0; c < 8; c++) M = fmaxf(M, g_pm[n * 8 + c]);
    float S = 0.f;
    #pragma unroll
    for (int c = 0; c < 8; c++) S += g_ps[n * 8 + c] * __expf(g_pm[n * 8 + c] - M);
    g_mx[n] = M;
    g_isum[n] = 1.f / S;
}

// ---------------- build G (tf32-rounded) ----------------
__global__ __launch_bounds__(96)
void gbuild_kernel(const int* __restrict__ tok, const float* __restrict__ emb)
{
    __shared__ float sal[NW + 2];
    __shared__ int stok[NW];
    const int b = blockIdx.x;
    const int tid = threadIdx.x;

    if (tid < NW) {
        sal[tid + 1] = __expf(g_aT[tid * B_SZ + b] - g_mx[tid]) * g_isum[tid];
        stok[tid] = tok[b * NW + tid];
    }
    if (tid == NW)     sal[0] = 0.f;
    if (tid == NW + 1) sal[NW + 1] = 0.f;
    __syncthreads();

    if (tid == 0) {
        float s = 0.f;
        #pragma unroll
        for (int n = 1; n <= NW; n++) s += sal[n];
        g_salpha[b] = s;
    }

    if (tid < WD / 4) {
        float4 g0 = make_float4(0.f, 0.f, 0.f, 0.f);
        float4 g1 = g0, g2 = g0;
        #pragma unroll
        for (int m = 0; m < NW; m++) {
            const float4 e = reinterpret_cast<const float4*>(
                emb + (size_t)stok[m] * WD)[tid];
            const float w1 = sal[m + 1];
            const float w0 = sal[m + 2];
            const float w2 = sal[m];
            g1.x += w1 * e.x; g1.y += w1 * e.y; g1.z += w1 * e.z; g1.w += w1 * e.w;
            g0.x += w0 * e.x; g0.y += w0 * e.y; g0.z += w0 * e.z; g0.w += w0 * e.w;
            g2.x += w2 * e.x; g2.y += w2 * e.y; g2.z += w2 * e.z; g2.w += w2 * e.w;
        }
        g0.x = rtf32(g0.x); g0.y = rtf32(g0.y); g0.z = rtf32(g0.z); g0.w = rtf32(g0.w);
        g1.x = rtf32(g1.x); g1.y = rtf32(g1.y); g1.z = rtf32(g1.z); g1.w = rtf32(g1.w);
        g2.x = rtf32(g2.x); g2.y = rtf32(g2.y); g2.z = rtf32(g2.z); g2.w = rtf32(g2.w);
        float4* gp = reinterpret_cast<float4*>(g_G + (size_t)b * 900);
        gp[tid]            = g0;
        gp[WD / 4 + tid]   = g1;
        gp[WD / 2 + tid]   = g2;
    }
}

// ---------------- launch ----------------
extern "C" void kernel_launch(void* const* d_in, const int* in_sizes, int n_in,
                              void* d_out, int out_size)
{
    const int*   tok    = (const int*)  d_in[0];
    const float* emb    = (const float*)d_in[1];
    const float* conv_w = (const float*)d_in[2];
    const float* conv_b = (const float*)d_in[3];
    const float* v      = (const float*)d_in[4];
    const float* vb     = (const float*)d_in[5];
    const float* q      = (const float*)d_in[6];
    float* out = (float*)d_out;

    float *pMpi, *pQ, *pG, *pWpi, *psal, *pembT;
    cudaGetSymbolAddress((void**)&pMpi,  g_Mpi);
    cudaGetSymbolAddress((void**)&pQ,    g_Q);
    cudaGetSymbolAddress((void**)&pG,    g_G);
    cudaGetSymbolAddress((void**)&pWpi,  g_Wpi);
    cudaGetSymbolAddress((void**)&psal,  g_salpha);
    cudaGetSymbolAddress((void**)&pembT, g_embT);

    cudaFuncSetAttribute(tgemm_kernel<80>,
                         cudaFuncAttributeMaxDynamicSharedMemorySize, SMEM3(80));

    // 1. prep (pair-interleaved B operands) + tf32-rounded emb copy
    prep_Mpi_kernel<<<(KQ_PAN * 8 * 2 * NQ_PAD + 255) / 256, 256>>>(conv_w, v);
    prep_cvb_kernel<<<1, 256>>>(conv_b, v, vb);
    prep_Wpi_kernel<<<(KF_PAN * 8 * 2 * CH + 255) / 256, 256>>>(conv_w);
    round_emb_kernel<<<(VOCAB * WD / 4 + 255) / 256, 256>>>(emb);

    // 2. Q = embT @ M : [32000,300] x [300,600]  (BN=80, 3 CTAs/SM, NP=640)
    {
        dim3 grid(NQ_PAD / 80, VOCAB / 128);
        tgemm_kernel<80><<<grid, 128, SMEM3(80)>>>(pembT, pMpi, pQ, VOCAB, 600, WD,
                                                   NQ_PAD, nullptr, nullptr);
    }

    // 3. attention scores
    score_kernel<<<B_SZ / 8, 256>>>(tok, q);

    // 4. softmax stats (two-stage)
    {
        dim3 pgrid(NW, 8);
        softmax_part_kernel<<<pgrid, 512>>>();
        softmax_comb_kernel<<<1, 32>>>();
    }

    // 5. build G (tf32-rounded) and sum-alpha
    gbuild_kernel<<<B_SZ, 96>>>(tok, emb);

    // 6. e = G @ Wc2 + salpha * conv_b : [32768,900] x [900,400]  (NP=400, BN=80)
    {
        dim3 grid(CH / 80, B_SZ / 128);
        tgemm_kernel<80><<<grid, 128, SMEM3(80)>>>(pG, pWpi, out, B_SZ, CH, 900,
                                                   CH, psal, conv_b);
    }
}

// round 11
// speedup vs baseline: 1.7132x; 1.0040x over previous
#include <cuda_runtime.h>
#include <cuda_fp16.h>
#include <math.h>
#include <stdint.h>

#define B_SZ   32768
#define NW     30
#define VOCAB  32000
#define WD     300
#define CH     400
#define AD     200

#define KQ_PAN 19      // ceil(300/16)
#define KF_PAN 57      // ceil(900/16)
#define NQ_PAD 640     // Q-gemm B rows padded (600 -> 640), multiple of 80

// ---------------- scratch (static device globals; no allocation) ----------------
__device__ __align__(16) float g_Mpi[KQ_PAN * 8 * 2 * NQ_PAD];   // pair-interleaved B (Q gemm)
__device__ __align__(16) float g_cvb[AD];
__device__ __align__(16) __half g_Qh[VOCAB * 600];               // fp16 Q table (38.4 MB)
__device__ __align__(16) float g_aT[NW * B_SZ];
__device__ float g_mx[NW];
__device__ float g_isum[NW];
__device__ float g_pm[NW * 8];
__device__ float g_ps[NW * 8];
__device__ __align__(16) float g_G[(size_t)B_SZ * 900];          // tf32-rounded [b][k*300+i]
__device__ float g_salpha[B_SZ];
__device__ __align__(16) float g_Wpi[KF_PAN * 8 * 2 * CH];       // pair-interleaved B (final)
__device__ __align__(16) float g_embT[VOCAB * WD];               // tf32-rounded emb copy

__device__ __forceinline__ uint32_t f2tf32(float x)
{
    uint32_t r;
    asm("cvt.rna.tf32.f32 %0, %1;" : "=r"(r) : "f"(x));
    return r;
}
__device__ __forceinline__ float rtf32(float x) { return __uint_as_float(f2tf32(x)); }

__device__ __forceinline__ float ftanh(float x)
{
    float e = __expf(2.f * x);
    return 1.f - __fdividef(2.f, e + 1.f);
}

// ---------------- prep kernels ----------------
// pair-interleaved B for Q gemm: element (k, n) of M[k=i][n=ks*200+a] stored at
// [panel=k/16][p = 4*((k%16)/8) + (k%4)][2n + ((k%8)/4)]
__global__ void prep_Mpi_kernel(const float* __restrict__ conv_w, const float* __restrict__ v)
{
    int idx = blockIdx.x * blockDim.x + threadIdx.x;
    if (idx >= KQ_PAN * 8 * 2 * NQ_PAD) return;
    const int pan = idx / (8 * 2 * NQ_PAD);
    const int rem = idx % (8 * 2 * NQ_PAD);
    const int p   = rem / (2 * NQ_PAD);
    const int c   = rem % (2 * NQ_PAD);
    const int n   = c >> 1;
    const int j   = c & 1;
    const int k   = pan * 16 + ((p >> 2) << 3) + (p & 3) + j * 4;   // logical K index (= i)
    float val = 0.f;
    if (k < WD && n < 600) {
        const int ks = n / 200;
        const int a  = n % 200;
        float s = 0.f;
        #pragma unroll 4
        for (int o = 0; o < CH; o++)
            s += conv_w[o * (WD * 3) + k * 3 + ks] * v[o * AD + a];
        val = rtf32(s);
    }
    g_Mpi[idx] = val;
}

// pair-interleaved B for final gemm: element (k, n=o) of Wc2[k = sl*300+i][o]
__global__ void prep_Wpi_kernel(const float* __restrict__ conv_w)
{
    int idx = blockIdx.x * blockDim.x + threadIdx.x;
    if (idx >= KF_PAN * 8 * 2 * CH) return;
    const int pan = idx / (8 * 2 * CH);
    const int rem = idx % (8 * 2 * CH);
    const int p   = rem / (2 * CH);
    const int c   = rem % (2 * CH);
    const int n   = c >> 1;
    const int j   = c & 1;
    const int k   = pan * 16 + ((p >> 2) << 3) + (p & 3) + j * 4;
    float val = 0.f;
    if (k < 900) {
        const int sl = k / WD;
        const int i  = k % WD;
        val = rtf32(conv_w[n * 900 + i * 3 + sl]);
    }
    g_Wpi[idx] = val;
}

__global__ void prep_cvb_kernel(const float* __restrict__ conv_b,
                                const float* __restrict__ v,
                                const float* __restrict__ vb)
{
    int a = blockIdx.x * blockDim.x + threadIdx.x;
    if (a >= AD) return;
    float s = vb[a];
    for (int o = 0; o < CH; o++) s += conv_b[o] * v[o * AD + a];
    g_cvb[a] = s;
}

__global__ void round_emb_kernel(const float* __restrict__ emb)
{
    int idx = blockIdx.x * blockDim.x + threadIdx.x;
    const int n4 = VOCAB * WD / 4;
    if (idx >= n4) return;
    float4 v = reinterpret_cast<const float4*>(emb)[idx];
    v.x = rtf32(v.x); v.y = rtf32(v.y); v.z = rtf32(v.z); v.w = rtf32(v.w);
    reinterpret_cast<float4*>(g_embT)[idx] = v;
}

// ---------------- tf32 mma.sync GEMM, pair-interleaved B, cp.async 4-stage -----
// C[M,N] = A[M,K] @ Bpi (+ rs[m]*bias[n]); A plain [M][K] tf32 bits (K clamped),
// Bpi pair-interleaved [K/16][8][2*NP] tf32 bits (zero-padded).
// HOUT=1: C is __half* (fp16 output). Block 128 x BN, 128 threads (4 warps 2x2).

__device__ __forceinline__ void mma_tf32(float* c,
                                         uint32_t a0, uint32_t a1, uint32_t a2, uint32_t a3,
                                         uint32_t b0, uint32_t b1)
{
    asm volatile(
        "mma.sync.aligned.m16n8k8.row.col.f32.tf32.tf32.f32 "
        "{%0,%1,%2,%3}, {%4,%5,%6,%7}, {%8,%9}, {%0,%1,%2,%3};\n"
        : "+f"(c[0]), "+f"(c[1]), "+f"(c[2]), "+f"(c[3])
        : "r"(a0), "r"(a1), "r"(a2), "r"(a3), "r"(b0), "r"(b1));
}

__device__ __forceinline__ void cp16z(uint32_t dst, const void* src, int bytes)
{
    asm volatile("cp.async.cg.shared.global [%0], [%1], 16, %2;\n"
                 :: "r"(dst), "l"(src), "r"(bytes));
}
__device__ __forceinline__ void cp16(uint32_t dst, const void* src)
{
    asm volatile("cp.async.cg.shared.global [%0], [%1], 16;\n"
                 :: "r"(dst), "l"(src));
}

#define STAGES 4
#define AS_W 20                 // 16 k + 4 pad

template<int BN, int HOUT>
__global__ __launch_bounds__(128, 3)
void tgemm_kernel(const float* __restrict__ A, const float* __restrict__ Bpi,
                  void* __restrict__ Cv, int M, int N, int K, int NP,
                  const float* __restrict__ rs, const float* __restrict__ bias)
{
    constexpr int BP_W  = 2 * BN + 8;            // smem words per pair-row
    constexpr int BCH   = 8 * (2 * BN) / 4;      // 16B chunks per B panel
    constexpr int BRND  = (BCH + 127) / 128;
    constexpr int NT    = BN / 16;

    extern __shared__ __align__(16) uint32_t smem[];
    uint32_t* Asm = smem;                            // [STAGES][128][AS_W]
    uint32_t* Bsm = smem + STAGES * 128 * AS_W;      // [STAGES][8][BP_W]
    const uint32_t as_base = (uint32_t)__cvta_generic_to_shared(Asm);
    const uint32_t bs_base = (uint32_t)__cvta_generic_to_shared(Bsm);

    const int tid    = threadIdx.x;
    const int lane   = tid & 31;
    const int warp   = tid >> 5;
    const int warp_m = warp & 1;
    const int warp_n = warp >> 1;
    const int m0 = blockIdx.y * 128;
    const int n0 = blockIdx.x * BN;

    const int am = tid >> 2;          // 0..31
    const int ak = (tid & 3) * 4;     // 0,4,8,12

    const int nIter = (K + 15) / 16;

    float acc[4][NT][4];
    #pragma unroll
    for (int mt = 0; mt < 4; mt++)
        #pragma unroll
        for (int nt = 0; nt < NT; nt++)
            #pragma unroll
            for (int i = 0; i < 4; i++) acc[mt][nt][i] = 0.f;

    auto issue_panel = [&](int pnl) {
        const int s   = pnl & (STAGES - 1);
        const int kk0 = pnl * 16;
        // A: 128 rows x 4 chunks of 16B (K-clamped, zero-filled)
        #pragma unroll
        for (int r = 0; r < 4; r++) {
            const int m  = am + r * 32;
            const int kg = kk0 + ak;
            int bytes = (K - kg) * 4;
            bytes = bytes < 0 ? 0 : (bytes > 16 ? 16 : bytes);
            const float* src = A + (size_t)(m0 + m) * K + (kg < K ? kg : 0);
            cp16z(as_base + (((s * 128 + m) * AS_W) + ak) * 4, src, bytes);
        }
        // B: pair-interleaved panel, 8 rows x 2*BN words (pre-padded; always valid)
        const float* bsrc0 = Bpi + ((size_t)pnl * 8) * (2 * NP) + 2 * n0;
        #pragma unroll
        for (int r = 0; r < BRND; r++) {
            const int idx = tid + r * 128;
            if (BCH % 128 == 0 || idx < BCH) {
                const int p  = idx / (2 * BN / 4);
                const int ch = idx % (2 * BN / 4);
                const float* src = bsrc0 + (size_t)p * (2 * NP) + ch * 4;
                cp16(bs_base + (((s * 8 + p) * BP_W) + ch * 4) * 4, src);
            }
        }
        asm volatile("cp.async.commit_group;\n");
    };

    issue_panel(0);
    issue_panel(1);
    issue_panel(2);

    for (int it = 0; it < nIter; ++it) {
        asm volatile("cp.async.wait_group %0;\n" :: "n"(STAGES - 2));
        __syncthreads();

        const int s = it & (STAGES - 1);
        const uint32_t* Asb = Asm + s * 128 * AS_W;
        const uint32_t* Bsb = Bsm + s * 8 * BP_W;

        #pragma unroll
        for (int ks = 0; ks < 2; ks++) {
            const int kb = ks * 8 + (lane & 3);
            const int pr = ks * 4 + (lane & 3);      // pair-row
            uint32_t af[4][4];
            uint32_t bf[NT][2];
            #pragma unroll
            for (int mt = 0; mt < 4; mt++) {
                const int rb = warp_m * 64 + mt * 16 + (lane >> 2);
                af[mt][0] = Asb[rb * AS_W + kb];
                af[mt][1] = Asb[(rb + 8) * AS_W + kb];
                af[mt][2] = Asb[rb * AS_W + kb + 4];
                af[mt][3] = Asb[(rb + 8) * AS_W + kb + 4];
            }
            #pragma unroll
            for (int nt = 0; nt < NT; nt++) {
                const int nc = warp_n * (BN / 2) + nt * 8 + (lane >> 2);
                uint2 bv = *reinterpret_cast<const uint2*>(&Bsb[pr * BP_W + nc * 2]);
                bf[nt][0] = bv.x;
                bf[nt][1] = bv.y;
            }
            #pragma unroll
            for (int mt = 0; mt < 4; mt++)
                #pragma unroll
                for (int nt = 0; nt < NT; nt++)
                    mma_tf32(acc[mt][nt], af[mt][0], af[mt][1], af[mt][2], af[mt][3],
                             bf[nt][0], bf[nt][1]);
        }

        if (it + STAGES - 1 < nIter) {
            issue_panel(it + STAGES - 1);
        } else {
            asm volatile("cp.async.commit_group;\n");
        }
    }

    // ---- epilogue ----
    #pragma unroll
    for (int mt = 0; mt < 4; mt++) {
        const int row0 = m0 + warp_m * 64 + mt * 16 + (lane >> 2);
        const int row1 = row0 + 8;
        const float r0 = rs ? rs[row0] : 0.f;
        const float r1 = rs ? rs[row1] : 0.f;
        #pragma unroll
        for (int nt = 0; nt < NT; nt++) {
            const int col = n0 + warp_n * (BN / 2) + nt * 8 + (lane & 3) * 2;
            if (col < N) {
                float v0 = acc[mt][nt][0], v1 = acc[mt][nt][1];
                float v2 = acc[mt][nt][2], v3 = acc[mt][nt][3];
                if (bias) {
                    const float b0 = bias[col], b1 = bias[col + 1];
                    v0 += r0 * b0; v1 += r0 * b1;
                    v2 += r1 * b0; v3 += r1 * b1;
                }
                if (HOUT) {
                    __half* Ch = (__half*)Cv;
                    *reinterpret_cast<__half2*>(Ch + (size_t)row0 * N + col) =
                        __floats2half2_rn(v0, v1);
                    *reinterpret_cast<__half2*>(Ch + (size_t)row1 * N + col) =
                        __floats2half2_rn(v2, v3);
                } else {
                    float* C = (float*)Cv;
                    *reinterpret_cast<float2*>(C + (size_t)row0 * N + col) = make_float2(v0, v1);
                    *reinterpret_cast<float2*>(C + (size_t)row1 * N + col) = make_float2(v2, v3);
                }
            }
        }
    }
}

#define SMEM3(BN) (STAGES * (128 * AS_W + 8 * (2 * (BN) + 8)) * 4)

// ---------------- scores: fp16 Q gathers ----------------
__global__ __launch_bounds__(256)
void score_kernel(const int* __restrict__ tok, const float* __restrict__ qv)
{
    __shared__ float4 sq[AD / 4];
    __shared__ float4 scvb[AD / 4];
    __shared__ int stok[8][NW];

    const int tid = threadIdx.x;
    const int wid = tid >> 5;
    const int lane = tid & 31;
    const int b = blockIdx.x * 8 + wid;

    if (tid < AD / 4) {
        sq[tid]   = reinterpret_cast<const float4*>(qv)[tid];
        scvb[tid] = reinterpret_cast<const float4*>(g_cvb)[tid];
    }
    if (lane < NW) stok[wid][lane] = tok[b * NW + lane];
    __syncthreads();

    for (int n = 0; n < NW; n++) {
        const int tc  = stok[wid][n];
        const int tp  = (n > 0)      ? stok[wid][n - 1] : -1;
        const int tn2 = (n < NW - 1) ? stok[wid][n + 1] : -1;
        // each uint2 chunk = 4 halfs; slices at +0, +200, +400 halfs (8B aligned)
        const uint2* q1 = reinterpret_cast<const uint2*>(g_Qh + (size_t)tc * 600 + 200);
        const uint2* q0 = (tp  >= 0) ? reinterpret_cast<const uint2*>(g_Qh + (size_t)tp  * 600)       : nullptr;
        const uint2* q2 = (tn2 >= 0) ? reinterpret_cast<const uint2*>(g_Qh + (size_t)tn2 * 600 + 400) : nullptr;

        float s = 0.f;
        #pragma unroll
        for (int a4 = lane; a4 < AD / 4; a4 += 32) {
            float4 h = scvb[a4];
            {
                uint2 u = q1[a4];
                float2 lo = __half22float2(*reinterpret_cast<__half2*>(&u.x));
                float2 hi = __half22float2(*reinterpret_cast<__half2*>(&u.y));
                h.x += lo.x; h.y += lo.y; h.z += hi.x; h.w += hi.y;
            }
            if (q0) {
                uint2 u = q0[a4];
                float2 lo = __half22float2(*reinterpret_cast<__half2*>(&u.x));
                float2 hi = __half22float2(*reinterpret_cast<__half2*>(&u.y));
                h.x += lo.x; h.y += lo.y; h.z += hi.x; h.w += hi.y;
            }
            if (q2) {
                uint2 u = q2[a4];
                float2 lo = __half22float2(*reinterpret_cast<__half2*>(&u.x));
                float2 hi = __half22float2(*reinterpret_cast<__half2*>(&u.y));
                h.x += lo.x; h.y += lo.y; h.z += hi.x; h.w += hi.y;
            }
            float4 qq = sq[a4];
            s += ftanh(h.x) * qq.x + ftanh(h.y) * qq.y + ftanh(h.z) * qq.z + ftanh(h.w) * qq.w;
        }
        #pragma unroll
        for (int off = 16; off; off >>= 1)
            s += __shfl_down_sync(0xffffffffu, s, off);
        if (lane == 0) g_aT[n * B_SZ + b] = s;
    }
}

// ---------------- two-stage softmax stats over batch axis ----------------
__global__ __launch_bounds__(512)
void softmax_part_kernel()
{
    __shared__ float red[512];
    const int n = blockIdx.x;
    const int c = blockIdx.y;
    const int tid = threadIdx.x;
    const float* row = g_aT + (size_t)n * B_SZ + c * 4096;

    float mx = -INFINITY;
    #pragma unroll
    for (int i = 0; i < 8; i++) mx = fmaxf(mx, row[tid + i * 512]);
    red[tid] = mx;
    __syncthreads();
    for (int s = 256; s > 0; s >>= 1) {
        if (tid < s) red[tid] = fmaxf(red[tid], red[tid + s]);
        __syncthreads();
    }
    mx = red[0];
    __syncthreads();

    float sum = 0.f;
    #pragma unroll
    for (int i = 0; i < 8; i++) sum += __expf(row[tid + i * 512] - mx);
    red[tid] = sum;
    __syncthreads();
    for (int s = 256; s > 0; s >>= 1) {
        if (tid < s) red[tid] += red[tid + s];
        __syncthreads();
    }
    if (tid == 0) { g_pm[n * 8 + c] = mx; g_ps[n * 8 + c] = red[0]; }
}

__global__ void softmax_comb_kernel()
{
    const int n = threadIdx.x;
    if (n >= NW) return;
    float M = -INFINITY;
    #pragma unroll
    for (int c = 0; c < 8; c++) M = fmaxf(M, g_pm[n * 8 + c]);
    float S = 0.f;
    #pragma unroll
    for (int c = 0; c < 8; c++) S += g_ps[n * 8 + c] * __expf(g_pm[n * 8 + c] - M);
    g_mx[n] = M;
    g_isum[n] = 1.f / S;
}

// ---------------- build G (tf32-rounded) ----------------
__global__ __launch_bounds__(96)
void gbuild_kernel(const int* __restrict__ tok, const float* __restrict__ emb)
{
    __shared__ float sal[NW + 2];
    __shared__ int stok[NW];
    const int b = blockIdx.x;
    const int tid = threadIdx.x;

    if (tid < NW) {
        sal[tid + 1] = __expf(g_aT[tid * B_SZ + b] - g_mx[tid]) * g_isum[tid];
        stok[tid] = tok[b * NW + tid];
    }
    if (tid == NW)     sal[0] = 0.f;
    if (tid == NW + 1) sal[NW + 1] = 0.f;
    __syncthreads();

    if (tid == 0) {
        float s = 0.f;
        #pragma unroll
        for (int n = 1; n <= NW; n++) s += sal[n];
        g_salpha[b] = s;
    }

    if (tid < WD / 4) {
        float4 g0 = make_float4(0.f, 0.f, 0.f, 0.f);
        float4 g1 = g0, g2 = g0;
        #pragma unroll
        for (int m = 0; m < NW; m++) {
            const float4 e = reinterpret_cast<const float4*>(
                emb + (size_t)stok[m] * WD)[tid];
            const float w1 = sal[m + 1];
            const float w0 = sal[m + 2];
            const float w2 = sal[m];
            g1.x += w1 * e.x; g1.y += w1 * e.y; g1.z += w1 * e.z; g1.w += w1 * e.w;
            g0.x += w0 * e.x; g0.y += w0 * e.y; g0.z += w0 * e.z; g0.w += w0 * e.w;
            g2.x += w2 * e.x; g2.y += w2 * e.y; g2.z += w2 * e.z; g2.w += w2 * e.w;
        }
        g0.x = rtf32(g0.x); g0.y = rtf32(g0.y); g0.z = rtf32(g0.z); g0.w = rtf32(g0.w);
        g1.x = rtf32(g1.x); g1.y = rtf32(g1.y); g1.z = rtf32(g1.z); g1.w = rtf32(g1.w);
        g2.x = rtf32(g2.x); g2.y = rtf32(g2.y); g2.z = rtf32(g2.z); g2.w = rtf32(g2.w);
        float4* gp = reinterpret_cast<float4*>(g_G + (size_t)b * 900);
        gp[tid]            = g0;
        gp[WD / 4 + tid]   = g1;
        gp[WD / 2 + tid]   = g2;
    }
}

// ---------------- launch ----------------
extern "C" void kernel_launch(void* const* d_in, const int* in_sizes, int n_in,
                              void* d_out, int out_size)
{
    const int*   tok    = (const int*)  d_in[0];
    const float* emb    = (const float*)d_in[1];
    const float* conv_w = (const float*)d_in[2];
    const float* conv_b = (const float*)d_in[3];
    const float* v      = (const float*)d_in[4];
    const float* vb     = (const float*)d_in[5];
    const float* q      = (const float*)d_in[6];
    float* out = (float*)d_out;

    float *pMpi, *pG, *pWpi, *psal, *pembT;
    __half* pQh;
    cudaGetSymbolAddress((void**)&pMpi,  g_Mpi);
    cudaGetSymbolAddress((void**)&pQh,   g_Qh);
    cudaGetSymbolAddress((void**)&pG,    g_G);
    cudaGetSymbolAddress((void**)&pWpi,  g_Wpi);
    cudaGetSymbolAddress((void**)&psal,  g_salpha);
    cudaGetSymbolAddress((void**)&pembT, g_embT);

    cudaFuncSetAttribute((const void*)tgemm_kernel<80, 0>,
                         cudaFuncAttributeMaxDynamicSharedMemorySize, SMEM3(80));
    cudaFuncSetAttribute((const void*)tgemm_kernel<80, 1>,
                         cudaFuncAttributeMaxDynamicSharedMemorySize, SMEM3(80));

    // 1. prep (pair-interleaved B operands) + tf32-rounded emb copy
    prep_Mpi_kernel<<<(KQ_PAN * 8 * 2 * NQ_PAD + 255) / 256, 256>>>(conv_w, v);
    prep_cvb_kernel<<<1, 256>>>(conv_b, v, vb);
    prep_Wpi_kernel<<<(KF_PAN * 8 * 2 * CH + 255) / 256, 256>>>(conv_w);
    round_emb_kernel<<<(VOCAB * WD / 4 + 255) / 256, 256>>>(emb);

    // 2. Q = embT @ M : [32000,300] x [300,600] -> fp16 Q table
    {
        dim3 grid(NQ_PAD / 80, VOCAB / 128);
        tgemm_kernel<80, 1><<<grid, 128, SMEM3(80)>>>(pembT, pMpi, (void*)pQh,
                                                      VOCAB, 600, WD, NQ_PAD,
                                                      nullptr, nullptr);
    }

    // 3. attention scores (fp16 gathers)
    score_kernel<<<B_SZ / 8, 256>>>(tok, q);

    // 4. softmax stats (two-stage)
    {
        dim3 pgrid(NW, 8);
        softmax_part_kernel<<<pgrid, 512>>>();
        softmax_comb_kernel<<<1, 32>>>();
    }

    // 5. build G (tf32-rounded) and sum-alpha
    gbuild_kernel<<<B_SZ, 96>>>(tok, emb);

    // 6. e = G @ Wc2 + salpha * conv_b : [32768,900] x [900,400]
    {
        dim3 grid(CH / 80, B_SZ / 128);
        tgemm_kernel<80, 0><<<grid, 128, SMEM3(80)>>>(pG, pWpi, (void*)out,
                                                      B_SZ, CH, 900, CH,
                                                      psal, conv_b);
    }
}